// round 1
// baseline (speedup 1.0000x reference)
#include <cuda_runtime.h>
#include <math.h>

// Problem constants
#define BATCH 4
#define AC 32          // input caps
#define BC 32          // output caps
#define PS 16          // psize
#define KK 9
#define KKA 288        // KK*AC
#define H 14
#define OH 7
#define L 49           // OH*OW
#define BL 196         // BATCH*L
#define NPP 3136       // BL*PS  (GEMM N)
#define EPSV 1e-12f
#define LN2PI 1.8378770664093453f

// ---------------- device scratch (static, no allocations) ----------------
__device__ float g_h[16][KKA];              // circulant kernels per p
__device__ float g_S[16];                   // sum_d h_p[d]
__device__ float g_Afull[16][KKA][KKA];     // I + circ(h_p)         5.3 MB
__device__ float g_PU[KKA][NPP];            // pose unfolded [m][bl*16+pp]  3.6 MB
__device__ float g_U[16][KKA][NPP];         // filtered pose          57.8 MB
__device__ float g_v[BL][KKA][BC][PS];      // votes                 115.6 MB
__device__ float g_au[BL][KKA];             // unfolded activations

// ---------------- kernel 0: build circulant kernels h_p, S_p ----------------
__global__ void k_build_h(const float* __restrict__ fw) {
    int p = blockIdx.x;          // 0..15
    int d = threadIdx.x;         // 0..287
    float wr0   = fw[(0 * 16 + p) * 2];
    float wr144 = fw[(144 * 16 + p) * 2];
    float s = 0.f;
    for (int k = 1; k <= 143; ++k) {
        float wr = fw[(k * 16 + p) * 2];
        float wi = fw[(k * 16 + p) * 2 + 1];
        int md = (k * d) % KKA;                  // exact phase reduction
        float x = (float)md * (1.0f / 144.0f);   // angle/pi
        float sn, cs;
        sincospif(x, &sn, &cs);
        s += wr * cs - wi * sn;
    }
    float h = (wr0 + ((d & 1) ? -wr144 : wr144) + 2.f * s) * (1.0f / (float)KKA);
    g_h[p][d] = h;
    __shared__ float red[KKA];
    red[d] = h;
    __syncthreads();
    if (d == 0) {
        float t = 0.f;
        for (int i = 0; i < KKA; ++i) t += red[i];
        g_S[p] = t;
    }
}

// ---------------- kernel 1: build A_p = I + circ(h_p) ----------------
__global__ void k_build_A() {
    int idx = blockIdx.x * blockDim.x + threadIdx.x;
    if (idx >= 16 * KKA * KKA) return;
    int p = idx / (KKA * KKA);
    int rem = idx - p * KKA * KKA;
    int k = rem / KKA;
    int m = rem - k * KKA;
    int d = k - m; if (d < 0) d += KKA;
    ((float*)g_Afull)[idx] = g_h[p][d] + (k == m ? 1.f : 0.f);
}

// ---------------- kernel 2: unfold pose -> PU, a_in -> au ----------------
__global__ void k_unfold(const float* __restrict__ pose, const float* __restrict__ a_in) {
    int idx = blockIdx.x * blockDim.x + threadIdx.x;   // m * BL*16 + bl*16 + pp
    if (idx >= KKA * BL * PS) return;
    int pp = idx & 15;
    int bl = (idx >> 4) % BL;
    int m  = idx / (BL * PS);
    int kk = m >> 5;          // /32
    int a  = m & 31;
    int batch = bl / L, pos = bl - batch * L;
    int y = pos / OH, x = pos - y * OH;
    int ki = kk / 3, kj = kk - ki * 3;
    int iy = y * 2 - 1 + ki;
    int ix = x * 2 - 1 + kj;
    bool ok = (iy >= 0) & (iy < H) & (ix >= 0) & (ix < H);
    float pv = ok ? pose[((batch * (AC * PS) + (a * PS + pp)) * H + iy) * H + ix] : 0.f;
    g_PU[m][bl * PS + pp] = pv;
    if (pp == 0) {
        float av = ok ? a_in[((batch * AC + a) * H + iy) * H + ix] : 0.f;
        g_au[bl][m] = av;
    }
}

// ---------------- kernel 3: 16 SGEMMs  U_p = A_p(288x288) @ PU(288x3136) ----
__global__ void k_gemm() {
    const int p = blockIdx.z;
    const float* __restrict__ Amat = &g_Afull[p][0][0];
    const float* __restrict__ Bmat = &g_PU[0][0];
    float* __restrict__ Cmat = &g_U[p][0][0];

    __shared__ float As[16][65];
    __shared__ float Bs[16][64];
    const int tid = threadIdx.x;       // 256
    const int row0 = blockIdx.y * 64;
    const int col0 = blockIdx.x * 64;
    const int a_r = tid >> 4, a_c = tid & 15;
    const int b_r = tid >> 6, b_c = tid & 63;
    const int ty = tid >> 4, tx = tid & 15;

    float acc[4][4];
#pragma unroll
    for (int i = 0; i < 4; ++i)
#pragma unroll
        for (int j = 0; j < 4; ++j) acc[i][j] = 0.f;

    for (int k0 = 0; k0 < KKA; k0 += 16) {
#pragma unroll
        for (int i = 0; i < 4; ++i) {
            int row = row0 + a_r + i * 16;
            As[a_c][a_r + i * 16] = (row < KKA) ? Amat[row * KKA + k0 + a_c] : 0.f;
        }
#pragma unroll
        for (int i = 0; i < 4; ++i)
            Bs[b_r + i * 4][b_c] = Bmat[(k0 + b_r + i * 4) * NPP + col0 + b_c];
        __syncthreads();
#pragma unroll
        for (int kk = 0; kk < 16; ++kk) {
            float ra[4], rb[4];
#pragma unroll
            for (int i = 0; i < 4; ++i) ra[i] = As[kk][ty * 4 + i];
#pragma unroll
            for (int j = 0; j < 4; ++j) rb[j] = Bs[kk][tx * 4 + j];
#pragma unroll
            for (int i = 0; i < 4; ++i)
#pragma unroll
                for (int j = 0; j < 4; ++j) acc[i][j] += ra[i] * rb[j];
        }
        __syncthreads();
    }
#pragma unroll
    for (int i = 0; i < 4; ++i) {
        int row = row0 + ty * 4 + i;
        if (row < KKA) {
#pragma unroll
            for (int j = 0; j < 4; ++j)
                Cmat[row * NPP + col0 + tx * 4 + j] = acc[i][j];
        }
    }
}

// ---------------- kernel 4: votes v[bl][k][b][p] ----------------
__global__ void k_votes(const float* __restrict__ W, const float* __restrict__ mb) {
    const int bl = blockIdx.x;        // 196
    const int tid = threadIdx.x;      // 512
    __shared__ float sWT[16][512];    // [pp][q]
    __shared__ float sb[512];
    __shared__ float UsT[16][17];     // [pp][p] padded
    for (int i = tid; i < 512 * 16; i += 512) {
        int q = i >> 4, pp = i & 15;
        sWT[pp][q] = W[q * 16 + pp];
    }
    sb[tid] = mb[tid] * (1.f + g_S[tid & 15]);
    __syncthreads();
    const int b = tid >> 4, p = tid & 15;
    for (int k = 0; k < KKA; ++k) {
        if (tid < 256) {
            int lp = tid >> 4, lpp = tid & 15;
            UsT[lpp][lp] = g_U[lp][k][bl * PS + lpp];
        }
        __syncthreads();
        float s = sb[tid];
#pragma unroll
        for (int pp = 0; pp < 16; ++pp) s += UsT[pp][p] * sWT[pp][tid];
        g_v[bl][k][b][p] = s;
        __syncthreads();
    }
}

// ---------------- kernel 5: fused EM routing (3 iters) + output ----------------
#define RIDX(k, b) ((k) * 33 + (b))
__global__ void k_em(const float* __restrict__ beta_u, const float* __restrict__ beta_a,
                     float* __restrict__ out) {
    const int bl = blockIdx.x;        // 196
    const int tid = threadIdx.x;      // 512
    __shared__ float r[KKA * 33];     // padded [k][b]
    __shared__ float au[KKA];
    __shared__ float rsum[32], invr[32], lsum2[32], loga[32], aouts[32];
    __shared__ float mu[32][16], sig[32][16], i2s[32][16];

    for (int i = tid; i < KKA; i += 512) au[i] = g_au[bl][i];
    for (int i = tid; i < KKA * 33; i += 512) r[i] = 1.0f / 32.0f;
    __syncthreads();

    const float* __restrict__ vbl = &g_v[bl][0][0][0];
    const int b = tid >> 4, p = tid & 15;
    const float LOG_LN2PI = logf(LN2PI);

    for (int it = 0; it < 3; ++it) {
        float lam = (it == 0) ? 5.0e-4f : (it == 1) ? 9.75e-4f : 1.42625e-3f;
        // r_sum
        if (tid < 32) {
            float s = 0.f;
            for (int k = 0; k < KKA; ++k) s += r[RIDX(k, tid)] * au[k];
            rsum[tid] = s;
            invr[tid] = 1.f / (s + EPSV);
        }
        __syncthreads();
        // mu pass
        {
            float acc = 0.f;
            float iv = invr[b];
            for (int k = 0; k < KKA; ++k) {
                float c = r[RIDX(k, b)] * au[k] * iv;
                acc += c * vbl[(k * 32 + b) * 16 + p];
            }
            mu[b][p] = acc;
        }
        __syncthreads();
        // sigma pass
        {
            float acc = 0.f;
            float m = mu[b][p];
            float iv = invr[b];
            for (int k = 0; k < KKA; ++k) {
                float c = r[RIDX(k, b)] * au[k] * iv;
                float d = vbl[(k * 32 + b) * 16 + p] - m;
                acc += c * d * d;
            }
            float sg = acc + EPSV;
            sig[b][p] = sg;
            i2s[b][p] = 0.5f / sg;
        }
        __syncthreads();
        // activations
        if (tid < 32) {
            float ls = 0.f;
            for (int q = 0; q < 16; ++q) ls += logf(sig[tid][q]);
            float cost = rsum[tid] * (16.f * beta_u[tid] + 0.5f * ls);
            float z = lam * (beta_a[tid] - cost);
            float ao = 1.f / (1.f + expf(-z));
            aouts[tid] = ao;
            loga[tid] = logf(ao);
            lsum2[tid] = ls + 16.f * LOG_LN2PI;
        }
        __syncthreads();
        if (it < 2) {
            // e-step: ln_ap into r buffer
            for (int i = tid; i < KKA * 32; i += 512) {
                int k = i >> 5, bb = i & 31;
                const float* vp = &vbl[(k * 32 + bb) * 16];
                float s = 0.f;
#pragma unroll
                for (int q = 0; q < 16; ++q) {
                    float d = vp[q] - mu[bb][q];
                    s += d * d * i2s[bb][q];
                }
                r[RIDX(k, bb)] = -0.5f * lsum2[bb] - s + loga[bb];
            }
            __syncthreads();
            // softmax over b per k
            if (tid < KKA) {
                int k = tid;
                float mx = -1e30f;
                for (int bb = 0; bb < 32; ++bb) mx = fmaxf(mx, r[RIDX(k, bb)]);
                float se = 0.f;
                for (int bb = 0; bb < 32; ++bb) se += expf(r[RIDX(k, bb)] - mx);
                float inv = 1.f / se;
                for (int bb = 0; bb < 32; ++bb)
                    r[RIDX(k, bb)] = expf(r[RIDX(k, bb)] - mx) * inv;
            }
            __syncthreads();
        }
    }
    // outputs: a_fin [BATCH][32][7][7] then pose_out [BATCH][512][7][7]
    int batch = bl / L, pos = bl - batch * L;
    if (tid < 32) out[(batch * 32 + tid) * L + pos] = aouts[tid];
    out[BATCH * 32 * L + (batch * 512 + tid) * L + pos] = mu[b][p];
}

// ---------------- launch ----------------
extern "C" void kernel_launch(void* const* d_in, const int* in_sizes, int n_in,
                              void* d_out, int out_size) {
    const float* a_in   = (const float*)d_in[0];
    const float* pose   = (const float*)d_in[1];
    const float* mposew = (const float*)d_in[2];
    const float* mposeb = (const float*)d_in[3];
    const float* freqw  = (const float*)d_in[4];
    const float* beta_u = (const float*)d_in[9];
    const float* beta_a = (const float*)d_in[10];
    float* out = (float*)d_out;

    k_build_h<<<16, KKA>>>(freqw);
    k_build_A<<<(16 * KKA * KKA + 255) / 256, 256>>>();
    k_unfold<<<(KKA * BL * PS + 255) / 256, 256>>>(pose, a_in);
    k_gemm<<<dim3(NPP / 64, (KKA + 63) / 64, 16), 256>>>();
    k_votes<<<BL, 512>>>(mposew, mposeb);
    k_em<<<BL, 512>>>(beta_u, beta_a, out);
}

// round 2
// speedup vs baseline: 1.5723x; 1.5723x over previous
#include <cuda_runtime.h>
#include <mma.h>
#include <math.h>

using namespace nvcuda;

// Problem constants
#define BATCH 4
#define AC 32
#define BC 32
#define PS 16
#define KK 9
#define KKA 288
#define H 14
#define OH 7
#define L 49
#define BL 196
#define NPP 3136        // real columns
#define NPAD 3200       // padded for BN=128 tiling
#define EPSV 1e-12f
#define LN2PI 1.8378770664093453f

// ---------------- device scratch ----------------
__device__ float g_h[16][KKA];            // circulant kernels per p
__device__ float g_S[16];                 // sum_d h_p[d]
__device__ float g_C[16][KKA][KKA];       // circ(h_p), tf32-rounded   5.3 MB
__device__ float g_PU[KKA][NPAD];         // pose unfolded (full fp32) 3.7 MB
__device__ float g_U[16][KKA][NPAD];      // C_h @ PU (correction)     59 MB
__device__ float g_v[BL][KKA][BC][PS];    // votes                     115.6 MB
__device__ float g_au[BL][KKA];

__device__ __forceinline__ float to_tf32(float x) {
    float r; asm("cvt.rna.tf32.f32 %0, %1;" : "=f"(r) : "f"(x)); return r;
}

// ---------------- kernel 0: circulant kernels h_p, S_p ----------------
__global__ void k_build_h(const float* __restrict__ fw) {
    int p = blockIdx.x;          // 0..15
    int d = threadIdx.x;         // 0..287
    float wr0   = fw[(0 * 16 + p) * 2];
    float wr144 = fw[(144 * 16 + p) * 2];
    float s = 0.f;
    for (int k = 1; k <= 143; ++k) {
        float wr = fw[(k * 16 + p) * 2];
        float wi = fw[(k * 16 + p) * 2 + 1];
        int md = (k * d) % KKA;
        float x = (float)md * (1.0f / 144.0f);
        float sn, cs;
        sincospif(x, &sn, &cs);
        s += wr * cs - wi * sn;
    }
    float h = (wr0 + ((d & 1) ? -wr144 : wr144) + 2.f * s) * (1.0f / (float)KKA);
    g_h[p][d] = h;
    __shared__ float red[KKA];
    red[d] = h;
    __syncthreads();
    if (d == 0) {
        float t = 0.f;
        for (int i = 0; i < KKA; ++i) t += red[i];
        g_S[p] = t;
    }
}

// ---------------- kernel 1: C_p = circ(h_p), tf32-rounded ----------------
__global__ void k_build_C() {
    int idx = blockIdx.x * blockDim.x + threadIdx.x;
    if (idx >= 16 * KKA * KKA) return;
    int p = idx / (KKA * KKA);
    int rem = idx - p * KKA * KKA;
    int k = rem / KKA;
    int m = rem - k * KKA;
    int d = k - m; if (d < 0) d += KKA;
    g_C[p][k][m] = to_tf32(g_h[p][d]);
}

// ---------------- kernel 2: unfold pose -> PU, a_in -> au ----------------
__global__ void k_unfold(const float* __restrict__ pose, const float* __restrict__ a_in) {
    int idx = blockIdx.x * blockDim.x + threadIdx.x;   // m * BL*16 + bl*16 + pp
    if (idx >= KKA * BL * PS) return;
    int pp = idx & 15;
    int bl = (idx >> 4) % BL;
    int m  = idx / (BL * PS);
    int kk = m >> 5;
    int a  = m & 31;
    int batch = bl / L, pos = bl - batch * L;
    int y = pos / OH, x = pos - y * OH;
    int ki = kk / 3, kj = kk - ki * 3;
    int iy = y * 2 - 1 + ki;
    int ix = x * 2 - 1 + kj;
    bool ok = (iy >= 0) & (iy < H) & (ix >= 0) & (ix < H);
    float pv = ok ? pose[((batch * (AC * PS) + (a * PS + pp)) * H + iy) * H + ix] : 0.f;
    g_PU[m][bl * PS + pp] = pv;
    if (pp == 0) {
        float av = ok ? a_in[((batch * AC + a) * H + iy) * H + ix] : 0.f;
        g_au[bl][m] = av;
    }
}

// ---------------- kernel 3: tf32 tensor GEMM  U_p = C_p @ PU ----------------
// grid (25, 3, 16), 256 threads. BM=96, BN=128, BK=32.
__global__ void k_gemm() {
    const int p    = blockIdx.z;
    const int row0 = blockIdx.y * 96;
    const int col0 = blockIdx.x * 128;
    __shared__ float sA[96][36];
    __shared__ float sB[32][132];
    const int tid = threadIdx.x;
    const int warpId = tid >> 5;
    const int wm = warpId & 1;        // 0..1 (48-row halves)
    const int wn = warpId >> 1;       // 0..3 (32-col quarters)

    wmma::fragment<wmma::accumulator, 16, 16, 8, float> acc[3][2];
#pragma unroll
    for (int i = 0; i < 3; ++i)
#pragma unroll
        for (int j = 0; j < 2; ++j) wmma::fill_fragment(acc[i][j], 0.f);

    for (int k0 = 0; k0 < KKA; k0 += 32) {
        // stage A: 96x32 (already tf32-rounded by producer)
#pragma unroll
        for (int i = tid; i < 768; i += 256) {
            int r = i >> 3, f = i & 7;
            float4 v = *(const float4*)&g_C[p][row0 + r][k0 + f * 4];
            *(float4*)&sA[r][f * 4] = v;
        }
        // stage B: 32x128, round to tf32 here
#pragma unroll
        for (int i = tid; i < 1024; i += 256) {
            int r = i >> 5, f = i & 31;
            float4 v = *(const float4*)&g_PU[k0 + r][col0 + f * 4];
            v.x = to_tf32(v.x); v.y = to_tf32(v.y);
            v.z = to_tf32(v.z); v.w = to_tf32(v.w);
            *(float4*)&sB[r][f * 4] = v;
        }
        __syncthreads();
#pragma unroll
        for (int ks = 0; ks < 4; ++ks) {
            wmma::fragment<wmma::matrix_a, 16, 16, 8, wmma::precision::tf32, wmma::row_major> af[3];
            wmma::fragment<wmma::matrix_b, 16, 16, 8, wmma::precision::tf32, wmma::row_major> bf[2];
#pragma unroll
            for (int i = 0; i < 3; ++i)
                wmma::load_matrix_sync(af[i], &sA[wm * 48 + i * 16][ks * 8], 36);
#pragma unroll
            for (int j = 0; j < 2; ++j)
                wmma::load_matrix_sync(bf[j], &sB[ks * 8][wn * 32 + j * 16], 132);
#pragma unroll
            for (int i = 0; i < 3; ++i)
#pragma unroll
                for (int j = 0; j < 2; ++j)
                    wmma::mma_sync(acc[i][j], af[i], bf[j], acc[i][j]);
        }
        __syncthreads();
    }
#pragma unroll
    for (int i = 0; i < 3; ++i)
#pragma unroll
        for (int j = 0; j < 2; ++j)
            wmma::store_matrix_sync(&g_U[p][row0 + wm * 48 + i * 16][col0 + wn * 32 + j * 16],
                                    acc[i][j], NPAD, wmma::mem_row_major);
}

// ---------------- kernel 4: votes v[bl][k][b][p] ----------------
// U_final = PU + C@PU added here; no per-k barriers, 9 k-chunks of 32.
__global__ void k_votes(const float* __restrict__ W, const float* __restrict__ mb) {
    const int bl = blockIdx.x;        // 196
    const int tid = threadIdx.x;      // 512
    __shared__ float Us[32][16][17];  // [k][pp][p] padded: 34.8 KB

    // W row for this (b,p) in registers
    float wreg[16];
    const float4* wv = (const float4*)(W + tid * 16);
#pragma unroll
    for (int f = 0; f < 4; ++f) {
        float4 w4 = wv[f];
        wreg[f * 4 + 0] = w4.x; wreg[f * 4 + 1] = w4.y;
        wreg[f * 4 + 2] = w4.z; wreg[f * 4 + 3] = w4.w;
    }
    const int b = tid >> 4, p = tid & 15;
    const float sbv = mb[tid] * (1.f + g_S[p]);
    const int col = bl * PS;

    for (int c = 0; c < 9; ++c) {
        int k0 = c * 32;
        __syncthreads();
        // stage: 32k x 16p x 16pp = 2048 float4 slots (4 floats each)
        for (int i = tid; i < 2048; i += 512) {
            int f = i & 3;                  // float4 within pp
            int pi = (i >> 2) & 15;         // which p-plane
            int k = i >> 6;                 // 0..31
            float4 u4 = *(const float4*)&g_U[pi][k0 + k][col + f * 4];
            float4 r4 = *(const float4*)&g_PU[k0 + k][col + f * 4];
            Us[k][f * 4 + 0][pi] = u4.x + r4.x;
            Us[k][f * 4 + 1][pi] = u4.y + r4.y;
            Us[k][f * 4 + 2][pi] = u4.z + r4.z;
            Us[k][f * 4 + 3][pi] = u4.w + r4.w;
        }
        __syncthreads();
#pragma unroll 4
        for (int k = 0; k < 32; ++k) {
            float s = sbv;
#pragma unroll
            for (int pp = 0; pp < 16; ++pp) s += Us[k][pp][p] * wreg[pp];
            g_v[bl][k0 + k][b][p] = s;
        }
    }
}

// ---------------- kernel 5: fused EM routing (3 iters) + output ----------------
#define RIDX(k, b) ((k) * 33 + (b))
__global__ void k_em(const float* __restrict__ beta_u, const float* __restrict__ beta_a,
                     float* __restrict__ out) {
    const int bl = blockIdx.x;        // 196
    const int tid = threadIdx.x;      // 512
    __shared__ float r[KKA * 33];     // 38 KB
    __shared__ float au[KKA];
    __shared__ float part[16][33];
    __shared__ float rsum[32], invr[32], lsum2[32], loga[32], aouts[32];
    __shared__ float mu[32][16], sig[32][16], i2s[32][16];

    for (int i = tid; i < KKA; i += 512) au[i] = g_au[bl][i];
    for (int i = tid; i < KKA * 33; i += 512) r[i] = 1.0f / 32.0f;
    __syncthreads();

    const float* __restrict__ vbl = &g_v[bl][0][0][0];
    const int b = tid >> 4, p = tid & 15;
    const int rb = tid & 31, rc = tid >> 5;   // for r_sum reduction
    const float LOG_LN2PI = logf(LN2PI);

    for (int it = 0; it < 3; ++it) {
        float lam = (it == 0) ? 5.0e-4f : (it == 1) ? 9.75e-4f : 1.42625e-3f;
        // r_sum: 16 chunks of 18 x 32 b
        {
            float s = 0.f;
#pragma unroll
            for (int j = 0; j < 18; ++j) {
                int k = rc * 18 + j;
                s += r[RIDX(k, rb)] * au[k];
            }
            part[rc][rb] = s;
        }
        __syncthreads();
        if (tid < 32) {
            float s = 0.f;
#pragma unroll
            for (int c = 0; c < 16; ++c) s += part[c][tid];
            rsum[tid] = s;
            invr[tid] = 1.f / (s + EPSV);
        }
        __syncthreads();
        // mu pass
        {
            float acc = 0.f;
            float iv = invr[b];
#pragma unroll 8
            for (int k = 0; k < KKA; ++k) {
                float c = r[RIDX(k, b)] * au[k];
                acc += c * vbl[(k * 32 + b) * 16 + p];
            }
            mu[b][p] = acc * iv;
        }
        __syncthreads();
        // sigma pass
        {
            float acc = 0.f;
            float m = mu[b][p];
            float iv = invr[b];
#pragma unroll 8
            for (int k = 0; k < KKA; ++k) {
                float c = r[RIDX(k, b)] * au[k];
                float d = vbl[(k * 32 + b) * 16 + p] - m;
                acc += c * d * d;
            }
            float sg = acc * iv + EPSV;
            sig[b][p] = sg;
            i2s[b][p] = 0.5f / sg;
        }
        __syncthreads();
        // activations
        if (tid < 32) {
            float ls = 0.f;
#pragma unroll
            for (int q = 0; q < 16; ++q) ls += logf(sig[tid][q]);
            float cost = rsum[tid] * (16.f * beta_u[tid] + 0.5f * ls);
            float z = lam * (beta_a[tid] - cost);
            float ao = 1.f / (1.f + expf(-z));
            aouts[tid] = ao;
            loga[tid] = logf(ao);
            lsum2[tid] = ls + 16.f * LOG_LN2PI;
        }
        __syncthreads();
        if (it < 2) {
            // e-step: ln_ap into r buffer
            for (int i = tid; i < KKA * 32; i += 512) {
                int k = i >> 5, bb = i & 31;
                const float4* vp = (const float4*)&vbl[(k * 32 + bb) * 16];
                float s = 0.f;
#pragma unroll
                for (int f = 0; f < 4; ++f) {
                    float4 v4 = vp[f];
                    float d0 = v4.x - mu[bb][f * 4 + 0];
                    float d1 = v4.y - mu[bb][f * 4 + 1];
                    float d2 = v4.z - mu[bb][f * 4 + 2];
                    float d3 = v4.w - mu[bb][f * 4 + 3];
                    s += d0 * d0 * i2s[bb][f * 4 + 0] + d1 * d1 * i2s[bb][f * 4 + 1]
                       + d2 * d2 * i2s[bb][f * 4 + 2] + d3 * d3 * i2s[bb][f * 4 + 3];
                }
                r[RIDX(k, bb)] = -0.5f * lsum2[bb] - s + loga[bb];
            }
            __syncthreads();
            // softmax over b per k
            if (tid < KKA) {
                int k = tid;
                float mx = -1e30f;
#pragma unroll
                for (int bb = 0; bb < 32; ++bb) mx = fmaxf(mx, r[RIDX(k, bb)]);
                float se = 0.f;
#pragma unroll
                for (int bb = 0; bb < 32; ++bb) {
                    float e = expf(r[RIDX(k, bb)] - mx);
                    r[RIDX(k, bb)] = e;
                    se += e;
                }
                float inv = 1.f / se;
#pragma unroll
                for (int bb = 0; bb < 32; ++bb) r[RIDX(k, bb)] *= inv;
            }
            __syncthreads();
        }
    }
    // outputs: a_fin [BATCH][32][7][7] then pose_out [BATCH][512][7][7]
    int batch = bl / L, pos = bl - batch * L;
    if (tid < 32) out[(batch * 32 + tid) * L + pos] = aouts[tid];
    out[BATCH * 32 * L + (batch * 512 + tid) * L + pos] = mu[b][p];
}

// ---------------- launch ----------------
extern "C" void kernel_launch(void* const* d_in, const int* in_sizes, int n_in,
                              void* d_out, int out_size) {
    const float* a_in   = (const float*)d_in[0];
    const float* pose   = (const float*)d_in[1];
    const float* mposew = (const float*)d_in[2];
    const float* mposeb = (const float*)d_in[3];
    const float* freqw  = (const float*)d_in[4];
    const float* beta_u = (const float*)d_in[9];
    const float* beta_a = (const float*)d_in[10];
    float* out = (float*)d_out;

    k_build_h<<<16, KKA>>>(freqw);
    k_build_C<<<(16 * KKA * KKA + 255) / 256, 256>>>();
    k_unfold<<<(KKA * BL * PS + 255) / 256, 256>>>(pose, a_in);
    k_gemm<<<dim3(NPAD / 128, KKA / 96, 16), 256>>>();
    k_votes<<<BL, 512>>>(mposew, mposeb);
    k_em<<<BL, 512>>>(beta_u, beta_a, out);
}

// round 4
// speedup vs baseline: 3.4772x; 2.2115x over previous
#include <cuda_runtime.h>
#include <cuda_fp16.h>
#include <mma.h>
#include <math.h>

using namespace nvcuda;

// Problem constants
#define BATCH 4
#define AC 32
#define BC 32
#define PS 16
#define KK 9
#define KKA 288
#define H 14
#define OH 7
#define L 49
#define BL 196
#define NPP 3136
#define NPAD 3200
#define GM 4608          // 16 * 288 fused GEMM M
#define EPSV 1e-12f
#define LN2PI 1.8378770664093453f

// ---------------- device scratch ----------------
__device__ float g_h[16][KKA];
__device__ float g_S[16];
__device__ __half g_Ch[GM][KKA];        // fp16 circulant correction rows (p*288+k)
__device__ float g_PU[KKA][NPAD];       // fp32 unfolded pose
__device__ __half g_PUh[KKA][NPAD];     // fp16 copy for GEMM
__device__ float g_U[16][KKA][NPAD];    // fp32 correction C@PU
__device__ float g_v[BL][KKA][BC][PS];  // votes
__device__ float g_au[BL][KKA];

__device__ __forceinline__ void cp16(void* smem_dst, const void* gsrc) {
    unsigned s = (unsigned)__cvta_generic_to_shared(smem_dst);
    asm volatile("cp.async.cg.shared.global [%0], [%1], 16;\n" :: "r"(s), "l"(gsrc));
}
#define CP_COMMIT() asm volatile("cp.async.commit_group;\n")
#define CP_WAIT(n)  asm volatile("cp.async.wait_group %0;\n" :: "n"(n))

// ---------------- kernel 0: circulant kernels h_p, S_p ----------------
__global__ void k_build_h(const float* __restrict__ fw) {
    int p = blockIdx.x;          // 0..15
    int d = threadIdx.x;         // 0..287
    float wr0   = fw[(0 * 16 + p) * 2];
    float wr144 = fw[(144 * 16 + p) * 2];
    float s = 0.f;
    for (int k = 1; k <= 143; ++k) {
        float wr = fw[(k * 16 + p) * 2];
        float wi = fw[(k * 16 + p) * 2 + 1];
        int md = (k * d) % KKA;
        float x = (float)md * (1.0f / 144.0f);
        float sn, cs;
        sincospif(x, &sn, &cs);
        s += wr * cs - wi * sn;
    }
    float h = (wr0 + ((d & 1) ? -wr144 : wr144) + 2.f * s) * (1.0f / (float)KKA);
    g_h[p][d] = h;
    __shared__ float red[KKA];
    red[d] = h;
    __syncthreads();
    if (d == 0) {
        float t = 0.f;
        for (int i = 0; i < KKA; ++i) t += red[i];
        g_S[p] = t;
    }
}

// ---------------- kernel 1: C rows (p*288+k), fp16 ----------------
__global__ void k_build_C() {
    int idx = blockIdx.x * blockDim.x + threadIdx.x;
    if (idx >= 16 * KKA * KKA) return;
    int p = idx / (KKA * KKA);
    int rem = idx - p * KKA * KKA;
    int k = rem / KKA;
    int m = rem - k * KKA;
    int d = k - m; if (d < 0) d += KKA;
    g_Ch[p * KKA + k][m] = __float2half(g_h[p][d]);
}

// ---------------- kernel 2: unfold pose -> PU (+fp16), a_in -> au ----------------
__global__ void k_unfold(const float* __restrict__ pose, const float* __restrict__ a_in) {
    int idx = blockIdx.x * blockDim.x + threadIdx.x;
    if (idx >= KKA * BL * PS) return;
    int pp = idx & 15;
    int bl = (idx >> 4) % BL;
    int m  = idx / (BL * PS);
    int kk = m >> 5;
    int a  = m & 31;
    int batch = bl / L, pos = bl - batch * L;
    int y = pos / OH, x = pos - y * OH;
    int ki = kk / 3, kj = kk - ki * 3;
    int iy = y * 2 - 1 + ki;
    int ix = x * 2 - 1 + kj;
    bool ok = (iy >= 0) & (iy < H) & (ix >= 0) & (ix < H);
    float pv = ok ? pose[((batch * (AC * PS) + (a * PS + pp)) * H + iy) * H + ix] : 0.f;
    g_PU[m][bl * PS + pp] = pv;
    g_PUh[m][bl * PS + pp] = __float2half(pv);
    if (pp == 0) {
        float av = ok ? a_in[((batch * AC + a) * H + iy) * H + ix] : 0.f;
        g_au[bl][m] = av;
    }
}

// ---------------- kernel 3: fp16 tensor GEMM  U = C(4608x288) @ PUh(288x3200) ----
// BM=128, BN=64, BK=32, 256 threads, cp.async double-buffered.
#define LDA 40
#define LDB 72
__global__ void k_gemm() {
    __shared__ __half sA[2][128 * LDA];
    __shared__ __half sB[2][32 * LDB];
    const int tid = threadIdx.x;
    const int row0 = blockIdx.y * 128;
    const int col0 = blockIdx.x * 64;
    const __half* Ag = &g_Ch[0][0];
    const __half* Bg = &g_PUh[0][0];
    const int wm = (tid >> 5) & 3;     // 0..3: 32-row stripes
    const int wn = tid >> 7;           // 0..1: 32-col stripes

    wmma::fragment<wmma::accumulator, 16, 16, 16, float> acc[2][2];
#pragma unroll
    for (int i = 0; i < 2; ++i)
#pragma unroll
        for (int j = 0; j < 2; ++j) wmma::fill_fragment(acc[i][j], 0.f);

    // prologue: stage 0, k0 = 0
    {
#pragma unroll
        for (int t = tid; t < 512; t += 256) {
            int r = t >> 2, c = t & 3;
            cp16(&sA[0][r * LDA + c * 8], Ag + (row0 + r) * KKA + c * 8);
        }
        int r = tid >> 3, c = tid & 7;
        cp16(&sB[0][r * LDB + c * 8], Bg + r * NPAD + col0 + c * 8);
        CP_COMMIT();
    }
    int cur = 0;
    for (int kt = 0; kt < 9; ++kt) {
        if (kt < 8) {
            int k0 = (kt + 1) * 32;
            int nxt = cur ^ 1;
#pragma unroll
            for (int t = tid; t < 512; t += 256) {
                int r = t >> 2, c = t & 3;
                cp16(&sA[nxt][r * LDA + c * 8], Ag + (row0 + r) * KKA + k0 + c * 8);
            }
            int r = tid >> 3, c = tid & 7;
            cp16(&sB[nxt][r * LDB + c * 8], Bg + (k0 + r) * NPAD + col0 + c * 8);
            CP_COMMIT();
            CP_WAIT(1);
        } else {
            CP_WAIT(0);
        }
        __syncthreads();
#pragma unroll
        for (int ks = 0; ks < 2; ++ks) {
            wmma::fragment<wmma::matrix_a, 16, 16, 16, __half, wmma::row_major> a0, a1;
            wmma::fragment<wmma::matrix_b, 16, 16, 16, __half, wmma::row_major> b0, b1;
            wmma::load_matrix_sync(a0, &sA[cur][(wm * 32) * LDA + ks * 16], LDA);
            wmma::load_matrix_sync(a1, &sA[cur][(wm * 32 + 16) * LDA + ks * 16], LDA);
            wmma::load_matrix_sync(b0, &sB[cur][(ks * 16) * LDB + wn * 32], LDB);
            wmma::load_matrix_sync(b1, &sB[cur][(ks * 16) * LDB + wn * 32 + 16], LDB);
            wmma::mma_sync(acc[0][0], a0, b0, acc[0][0]);
            wmma::mma_sync(acc[0][1], a0, b1, acc[0][1]);
            wmma::mma_sync(acc[1][0], a1, b0, acc[1][0]);
            wmma::mma_sync(acc[1][1], a1, b1, acc[1][1]);
        }
        __syncthreads();
        cur ^= 1;
    }
    float* Uf = &g_U[0][0][0];
#pragma unroll
    for (int i = 0; i < 2; ++i)
#pragma unroll
        for (int j = 0; j < 2; ++j)
            wmma::store_matrix_sync(Uf + (size_t)(row0 + wm * 32 + i * 16) * NPAD
                                       + col0 + wn * 32 + j * 16,
                                    acc[i][j], NPAD, wmma::mem_row_major);
}

// ---------------- kernel 4: votes v[bl][k][b][p], grid (196, 3) ----------------
__global__ void k_votes(const float* __restrict__ W, const float* __restrict__ mb) {
    const int bl = blockIdx.x;
    const int cg = blockIdx.y;        // 0..2 -> 3 chunks of 3 k-tiles
    const int tid = threadIdx.x;      // 512
    __shared__ float Us[32][16][17];

    float wreg[16];
    const float4* wv = (const float4*)(W + tid * 16);
#pragma unroll
    for (int f = 0; f < 4; ++f) {
        float4 w4 = wv[f];
        wreg[f * 4 + 0] = w4.x; wreg[f * 4 + 1] = w4.y;
        wreg[f * 4 + 2] = w4.z; wreg[f * 4 + 3] = w4.w;
    }
    const int b = tid >> 4, p = tid & 15;
    const float sbv = mb[tid] * (1.f + g_S[p]);
    const int col = bl * PS;

    for (int j = 0; j < 3; ++j) {
        int k0 = (cg * 3 + j) * 32;
        __syncthreads();
        for (int i = tid; i < 2048; i += 512) {
            int f = i & 3;
            int pi = (i >> 2) & 15;
            int k = i >> 6;
            float4 u4 = *(const float4*)&g_U[pi][k0 + k][col + f * 4];
            float4 r4 = *(const float4*)&g_PU[k0 + k][col + f * 4];
            Us[k][f * 4 + 0][pi] = u4.x + r4.x;
            Us[k][f * 4 + 1][pi] = u4.y + r4.y;
            Us[k][f * 4 + 2][pi] = u4.z + r4.z;
            Us[k][f * 4 + 3][pi] = u4.w + r4.w;
        }
        __syncthreads();
#pragma unroll 4
        for (int k = 0; k < 32; ++k) {
            float s = sbv;
#pragma unroll
            for (int pp = 0; pp < 16; ++pp) s += Us[k][pp][p] * wreg[pp];
            g_v[bl][k0 + k][b][p] = s;
        }
    }
}

// ---------------- kernel 5: fused EM routing, 3 v-passes total ----------------
__global__ void k_em(const float* __restrict__ beta_u, const float* __restrict__ beta_a,
                     float* __restrict__ out) {
    const int bl = blockIdx.x;        // 196
    const int tid = threadIdx.x;      // 512
    const int warp = tid >> 5, lane = tid & 31;
    __shared__ float au[KKA];
    __shared__ float accv[32][17], acc2[32][17];
    __shared__ float accr[32];
    __shared__ float mu[32][17], i2s[32][17], sigs[32][17];
    __shared__ float lsum2[32], loga[32], aouts[32], rsum_sh[32];
    __shared__ float wred[16];
    __shared__ float sau_sh;

    for (int i = tid; i < KKA; i += 512) au[i] = g_au[bl][i];
    for (int i = tid; i < 32 * 17; i += 512) { (&accv[0][0])[i] = 0.f; (&acc2[0][0])[i] = 0.f; }
    __syncthreads();
    // sum of au
    {
        float s = (tid < KKA) ? au[tid] : 0.f;
#pragma unroll
        for (int o = 16; o; o >>= 1) s += __shfl_xor_sync(~0u, s, o);
        if (lane == 0) wred[warp] = s;
        __syncthreads();
        if (tid == 0) { float t = 0.f; for (int i = 0; i < 16; ++i) t += wred[i]; sau_sh = t; }
        __syncthreads();
    }
    const float* __restrict__ vbl = &g_v[bl][0][0][0];
    const int b = tid >> 4, q = tid & 15;
    const float LOG_LN2PI = logf(LN2PI);

    // ---- pass 0: uniform r = 1/32 ----
    {
        float av[16], a2[16];
#pragma unroll
        for (int j = 0; j < 16; ++j) { av[j] = 0.f; a2[j] = 0.f; }
        for (int k = warp; k < KKA; k += 16) {
            float c = au[k];
            const float4* vp = (const float4*)&vbl[(k * 32 + lane) * 16];
#pragma unroll
            for (int f = 0; f < 4; ++f) {
                float4 v4 = vp[f];
                av[f * 4 + 0] += c * v4.x; a2[f * 4 + 0] += c * v4.x * v4.x;
                av[f * 4 + 1] += c * v4.y; a2[f * 4 + 1] += c * v4.y * v4.y;
                av[f * 4 + 2] += c * v4.z; a2[f * 4 + 2] += c * v4.z * v4.z;
                av[f * 4 + 3] += c * v4.w; a2[f * 4 + 3] += c * v4.w * v4.w;
            }
        }
#pragma unroll
        for (int j = 0; j < 16; ++j) {
            atomicAdd(&accv[lane][j], av[j]);
            atomicAdd(&acc2[lane][j], a2[j]);
        }
    }
    __syncthreads();
    // finalize iter 0 (uniform r: rs is b-independent)
    {
        float rs = sau_sh * (1.f / 32.f);
        float iv = 1.f / (rs + EPSV);
        float m  = accv[b][q] * (1.f / 32.f) * iv;
        float sg = acc2[b][q] * (1.f / 32.f) * iv - m * m + EPSV;
        mu[b][q] = m; sigs[b][q] = sg; i2s[b][q] = 0.5f / sg;
        if (tid < 32) rsum_sh[tid] = rs;
    }
    __syncthreads();
    if (tid < 32) {
        float ls = 0.f;
#pragma unroll
        for (int j = 0; j < 16; ++j) ls += logf(sigs[tid][j]);
        float cost = rsum_sh[tid] * (16.f * beta_u[tid] + 0.5f * ls);
        float z = 5.0e-4f * (beta_a[tid] - cost);
        float ao = 1.f / (1.f + expf(-z));
        aouts[tid] = ao; loga[tid] = logf(ao);
        lsum2[tid] = ls + 16.f * LOG_LN2PI;
    }
    __syncthreads();

    // ---- fused passes: e-step(it) + stats(it+1), it = 0, 1 ----
#pragma unroll 1
    for (int it = 0; it < 2; ++it) {
        for (int i = tid; i < 32 * 17; i += 512) { (&accv[0][0])[i] = 0.f; (&acc2[0][0])[i] = 0.f; }
        if (tid < 32) accr[tid] = 0.f;
        __syncthreads();
        float av[16], a2[16], ar = 0.f;
#pragma unroll
        for (int j = 0; j < 16; ++j) { av[j] = 0.f; a2[j] = 0.f; }
        const float myl2 = lsum2[lane];
        const float mylg = loga[lane];
        for (int k = warp; k < KKA; k += 16) {
            const float4* vp = (const float4*)&vbl[(k * 32 + lane) * 16];
            float4 v0 = vp[0], v1 = vp[1], v2 = vp[2], v3 = vp[3];
            float s = 0.f, d;
            d = v0.x - mu[lane][ 0]; s += d * d * i2s[lane][ 0];
            d = v0.y - mu[lane][ 1]; s += d * d * i2s[lane][ 1];
            d = v0.z - mu[lane][ 2]; s += d * d * i2s[lane][ 2];
            d = v0.w - mu[lane][ 3]; s += d * d * i2s[lane][ 3];
            d = v1.x - mu[lane][ 4]; s += d * d * i2s[lane][ 4];
            d = v1.y - mu[lane][ 5]; s += d * d * i2s[lane][ 5];
            d = v1.z - mu[lane][ 6]; s += d * d * i2s[lane][ 6];
            d = v1.w - mu[lane][ 7]; s += d * d * i2s[lane][ 7];
            d = v2.x - mu[lane][ 8]; s += d * d * i2s[lane][ 8];
            d = v2.y - mu[lane][ 9]; s += d * d * i2s[lane][ 9];
            d = v2.z - mu[lane][10]; s += d * d * i2s[lane][10];
            d = v2.w - mu[lane][11]; s += d * d * i2s[lane][11];
            d = v3.x - mu[lane][12]; s += d * d * i2s[lane][12];
            d = v3.y - mu[lane][13]; s += d * d * i2s[lane][13];
            d = v3.z - mu[lane][14]; s += d * d * i2s[lane][14];
            d = v3.w - mu[lane][15]; s += d * d * i2s[lane][15];
            float lnap = -0.5f * myl2 - s + mylg;
            float mx = lnap;
#pragma unroll
            for (int o = 16; o; o >>= 1) mx = fmaxf(mx, __shfl_xor_sync(~0u, mx, o));
            float e = expf(lnap - mx);
            float se = e;
#pragma unroll
            for (int o = 16; o; o >>= 1) se += __shfl_xor_sync(~0u, se, o);
            float c = (e / se) * au[k];
            ar += c;
            av[ 0] += c * v0.x; a2[ 0] += c * v0.x * v0.x;
            av[ 1] += c * v0.y; a2[ 1] += c * v0.y * v0.y;
            av[ 2] += c * v0.z; a2[ 2] += c * v0.z * v0.z;
            av[ 3] += c * v0.w; a2[ 3] += c * v0.w * v0.w;
            av[ 4] += c * v1.x; a2[ 4] += c * v1.x * v1.x;
            av[ 5] += c * v1.y; a2[ 5] += c * v1.y * v1.y;
            av[ 6] += c * v1.z; a2[ 6] += c * v1.z * v1.z;
            av[ 7] += c * v1.w; a2[ 7] += c * v1.w * v1.w;
            av[ 8] += c * v2.x; a2[ 8] += c * v2.x * v2.x;
            av[ 9] += c * v2.y; a2[ 9] += c * v2.y * v2.y;
            av[10] += c * v2.z; a2[10] += c * v2.z * v2.z;
            av[11] += c * v2.w; a2[11] += c * v2.w * v2.w;
            av[12] += c * v3.x; a2[12] += c * v3.x * v3.x;
            av[13] += c * v3.y; a2[13] += c * v3.y * v3.y;
            av[14] += c * v3.z; a2[14] += c * v3.z * v3.z;
            av[15] += c * v3.w; a2[15] += c * v3.w * v3.w;
        }
#pragma unroll
        for (int j = 0; j < 16; ++j) {
            atomicAdd(&accv[lane][j], av[j]);
            atomicAdd(&acc2[lane][j], a2[j]);
        }
        atomicAdd(&accr[lane], ar);
        __syncthreads();
        // finalize iter it+1  (FIX: rsum_sh[tid] = accr[tid], not accr[tid>>4])
        {
            float rs = accr[b];
            float iv = 1.f / (rs + EPSV);
            float m  = accv[b][q] * iv;
            float sg = acc2[b][q] * iv - m * m + EPSV;
            mu[b][q] = m; sigs[b][q] = sg; i2s[b][q] = 0.5f / sg;
            if (tid < 32) rsum_sh[tid] = accr[tid];
        }
        __syncthreads();
        if (tid < 32) {
            float ls = 0.f;
#pragma unroll
            for (int j = 0; j < 16; ++j) ls += logf(sigs[tid][j]);
            float cost = rsum_sh[tid] * (16.f * beta_u[tid] + 0.5f * ls);
            float lam = (it == 0) ? 9.75e-4f : 1.42625e-3f;
            float z = lam * (beta_a[tid] - cost);
            float ao = 1.f / (1.f + expf(-z));
            aouts[tid] = ao; loga[tid] = logf(ao);
            lsum2[tid] = ls + 16.f * LOG_LN2PI;
        }
        __syncthreads();
    }
    // outputs: a_fin [BATCH][32][7][7] then pose_out [BATCH][512][7][7]
    int batch = bl / L, pos = bl - batch * L;
    if (tid < 32) out[(batch * 32 + tid) * L + pos] = aouts[tid];
    out[BATCH * 32 * L + (batch * 512 + tid) * L + pos] = mu[b][q];
}

// ---------------- launch ----------------
extern "C" void kernel_launch(void* const* d_in, const int* in_sizes, int n_in,
                              void* d_out, int out_size) {
    const float* a_in   = (const float*)d_in[0];
    const float* pose   = (const float*)d_in[1];
    const float* mposew = (const float*)d_in[2];
    const float* mposeb = (const float*)d_in[3];
    const float* freqw  = (const float*)d_in[4];
    const float* beta_u = (const float*)d_in[9];
    const float* beta_a = (const float*)d_in[10];
    float* out = (float*)d_out;

    k_build_h<<<16, KKA>>>(freqw);
    k_build_C<<<(16 * KKA * KKA + 255) / 256, 256>>>();
    k_unfold<<<(KKA * BL * PS + 255) / 256, 256>>>(pose, a_in);
    k_gemm<<<dim3(NPAD / 64, GM / 128), 256>>>();
    k_votes<<<dim3(BL, 3), 512>>>(mposew, mposeb);
    k_em<<<BL, 512>>>(beta_u, beta_a, out);
}

// round 5
// speedup vs baseline: 4.0119x; 1.1538x over previous
#include <cuda_runtime.h>
#include <cuda_fp16.h>
#include <mma.h>
#include <math.h>

using namespace nvcuda;

// Problem constants
#define BATCH 4
#define AC 32
#define BC 32
#define PS 16
#define KK 9
#define KKA 288
#define H 14
#define OH 7
#define L 49
#define BL 196
#define NPP 3136
#define NPAD 3200
#define GM 4608          // 16 * 288 fused GEMM M
#define EPSV 1e-12f
#define LN2PI 1.8378770664093453f

// ---------------- device scratch ----------------
__device__ float g_h[16][KKA];
__device__ float g_S[16];
__device__ __half g_Ch[GM][KKA];        // fp16 circulant correction rows (p*288+k)
__device__ float g_PU[KKA][NPAD];       // fp32 unfolded pose
__device__ __half g_PUh[KKA][NPAD];     // fp16 copy for GEMM
__device__ float g_U[16][KKA][NPAD];    // fp32 correction C@PU
__device__ __half g_vh[BL][KKA][BC][PS];// votes, fp16 (57.8 MB)
__device__ float g_au[BL][KKA];
__device__ float g_pass0[BL][2][512];   // pass-0 stats: [0]=sum au*v, [1]=sum au*v^2

__device__ __forceinline__ void cp16(void* smem_dst, const void* gsrc) {
    unsigned s = (unsigned)__cvta_generic_to_shared(smem_dst);
    asm volatile("cp.async.cg.shared.global [%0], [%1], 16;\n" :: "r"(s), "l"(gsrc));
}
#define CP_COMMIT() asm volatile("cp.async.commit_group;\n")
#define CP_WAIT(n)  asm volatile("cp.async.wait_group %0;\n" :: "n"(n))

// ---------------- kernel 0: circulant kernels h_p, S_p ----------------
__global__ void k_build_h(const float* __restrict__ fw) {
    int p = blockIdx.x;          // 0..15
    int d = threadIdx.x;         // 0..287
    float wr0   = fw[(0 * 16 + p) * 2];
    float wr144 = fw[(144 * 16 + p) * 2];
    float s = 0.f;
    for (int k = 1; k <= 143; ++k) {
        float wr = fw[(k * 16 + p) * 2];
        float wi = fw[(k * 16 + p) * 2 + 1];
        int md = (k * d) % KKA;
        float x = (float)md * (1.0f / 144.0f);
        float sn, cs;
        sincospif(x, &sn, &cs);
        s += wr * cs - wi * sn;
    }
    float h = (wr0 + ((d & 1) ? -wr144 : wr144) + 2.f * s) * (1.0f / (float)KKA);
    g_h[p][d] = h;
    __shared__ float red[KKA];
    red[d] = h;
    __syncthreads();
    if (d == 0) {
        float t = 0.f;
        for (int i = 0; i < KKA; ++i) t += red[i];
        g_S[p] = t;
    }
}

// ---------------- kernel 1: C rows (p*288+k), fp16 ----------------
__global__ void k_build_C() {
    int idx = blockIdx.x * blockDim.x + threadIdx.x;
    if (idx >= 16 * KKA * KKA) return;
    int p = idx / (KKA * KKA);
    int rem = idx - p * KKA * KKA;
    int k = rem / KKA;
    int m = rem - k * KKA;
    int d = k - m; if (d < 0) d += KKA;
    g_Ch[p * KKA + k][m] = __float2half(g_h[p][d]);
}

// ---------------- kernel 2: unfold pose -> PU (+fp16), a_in -> au; zero pass0 ----
__global__ void k_unfold(const float* __restrict__ pose, const float* __restrict__ a_in) {
    int idx = blockIdx.x * blockDim.x + threadIdx.x;
    if (idx < BL * 2 * 512) ((float*)g_pass0)[idx] = 0.f;
    if (idx >= KKA * BL * PS) return;
    int pp = idx & 15;
    int bl = (idx >> 4) % BL;
    int m  = idx / (BL * PS);
    int kk = m >> 5;
    int a  = m & 31;
    int batch = bl / L, pos = bl - batch * L;
    int y = pos / OH, x = pos - y * OH;
    int ki = kk / 3, kj = kk - ki * 3;
    int iy = y * 2 - 1 + ki;
    int ix = x * 2 - 1 + kj;
    bool ok = (iy >= 0) & (iy < H) & (ix >= 0) & (ix < H);
    float pv = ok ? pose[((batch * (AC * PS) + (a * PS + pp)) * H + iy) * H + ix] : 0.f;
    g_PU[m][bl * PS + pp] = pv;
    g_PUh[m][bl * PS + pp] = __float2half(pv);
    if (pp == 0) {
        float av = ok ? a_in[((batch * AC + a) * H + iy) * H + ix] : 0.f;
        g_au[bl][m] = av;
    }
}

// ---------------- kernel 3: fp16 tensor GEMM  U = C(4608x288) @ PUh(288x3200) ----
// BM=128, BN=64, BK=32, 256 threads, cp.async double-buffered.
#define LDA 40
#define LDB 72
__global__ void k_gemm() {
    __shared__ __half sA[2][128 * LDA];
    __shared__ __half sB[2][32 * LDB];
    const int tid = threadIdx.x;
    const int row0 = blockIdx.y * 128;
    const int col0 = blockIdx.x * 64;
    const __half* Ag = &g_Ch[0][0];
    const __half* Bg = &g_PUh[0][0];
    const int wm = (tid >> 5) & 3;     // 0..3: 32-row stripes
    const int wn = tid >> 7;           // 0..1: 32-col stripes

    wmma::fragment<wmma::accumulator, 16, 16, 16, float> acc[2][2];
#pragma unroll
    for (int i = 0; i < 2; ++i)
#pragma unroll
        for (int j = 0; j < 2; ++j) wmma::fill_fragment(acc[i][j], 0.f);

    {
#pragma unroll
        for (int t = tid; t < 512; t += 256) {
            int r = t >> 2, c = t & 3;
            cp16(&sA[0][r * LDA + c * 8], Ag + (row0 + r) * KKA + c * 8);
        }
        int r = tid >> 3, c = tid & 7;
        cp16(&sB[0][r * LDB + c * 8], Bg + r * NPAD + col0 + c * 8);
        CP_COMMIT();
    }
    int cur = 0;
    for (int kt = 0; kt < 9; ++kt) {
        if (kt < 8) {
            int k0 = (kt + 1) * 32;
            int nxt = cur ^ 1;
#pragma unroll
            for (int t = tid; t < 512; t += 256) {
                int r = t >> 2, c = t & 3;
                cp16(&sA[nxt][r * LDA + c * 8], Ag + (row0 + r) * KKA + k0 + c * 8);
            }
            int r = tid >> 3, c = tid & 7;
            cp16(&sB[nxt][r * LDB + c * 8], Bg + (k0 + r) * NPAD + col0 + c * 8);
            CP_COMMIT();
            CP_WAIT(1);
        } else {
            CP_WAIT(0);
        }
        __syncthreads();
#pragma unroll
        for (int ks = 0; ks < 2; ++ks) {
            wmma::fragment<wmma::matrix_a, 16, 16, 16, __half, wmma::row_major> a0, a1;
            wmma::fragment<wmma::matrix_b, 16, 16, 16, __half, wmma::row_major> b0, b1;
            wmma::load_matrix_sync(a0, &sA[cur][(wm * 32) * LDA + ks * 16], LDA);
            wmma::load_matrix_sync(a1, &sA[cur][(wm * 32 + 16) * LDA + ks * 16], LDA);
            wmma::load_matrix_sync(b0, &sB[cur][(ks * 16) * LDB + wn * 32], LDB);
            wmma::load_matrix_sync(b1, &sB[cur][(ks * 16) * LDB + wn * 32 + 16], LDB);
            wmma::mma_sync(acc[0][0], a0, b0, acc[0][0]);
            wmma::mma_sync(acc[0][1], a0, b1, acc[0][1]);
            wmma::mma_sync(acc[1][0], a1, b0, acc[1][0]);
            wmma::mma_sync(acc[1][1], a1, b1, acc[1][1]);
        }
        __syncthreads();
        cur ^= 1;
    }
    float* Uf = &g_U[0][0][0];
#pragma unroll
    for (int i = 0; i < 2; ++i)
#pragma unroll
        for (int j = 0; j < 2; ++j)
            wmma::store_matrix_sync(Uf + (size_t)(row0 + wm * 32 + i * 16) * NPAD
                                       + col0 + wn * 32 + j * 16,
                                    acc[i][j], NPAD, wmma::mem_row_major);
}

// ---------------- kernel 4: votes (fp16) + EM pass-0 stats, grid (196, 3) ------
__global__ void k_votes(const float* __restrict__ W, const float* __restrict__ mb) {
    const int bl = blockIdx.x;
    const int cg = blockIdx.y;        // 0..2 -> 96 k each
    const int tid = threadIdx.x;      // 512
    __shared__ __align__(16) float Usf[32][16][20];   // [k][p_filter][pp], pad 20
    __shared__ float sau[96];

    float wreg[16];
    const float4* wv = (const float4*)(W + tid * 16);
#pragma unroll
    for (int f = 0; f < 4; ++f) {
        float4 w4 = wv[f];
        wreg[f * 4 + 0] = w4.x; wreg[f * 4 + 1] = w4.y;
        wreg[f * 4 + 2] = w4.z; wreg[f * 4 + 3] = w4.w;
    }
    if (tid < 96) sau[tid] = g_au[bl][cg * 96 + tid];
    const int b = tid >> 4, p = tid & 15;
    const float sbv = mb[tid] * (1.f + g_S[p]);
    const int col = bl * PS;

    float aV = 0.f, aQ = 0.f;
    for (int j = 0; j < 3; ++j) {
        int k0 = cg * 96 + j * 32;
        __syncthreads();
        for (int i = tid; i < 2048; i += 512) {
            int f = i & 3;
            int pf = (i >> 2) & 15;
            int k = i >> 6;
            float4 u4 = *(const float4*)&g_U[pf][k0 + k][col + f * 4];
            float4 r4 = *(const float4*)&g_PU[k0 + k][col + f * 4];
            float4 y;
            y.x = u4.x + r4.x; y.y = u4.y + r4.y;
            y.z = u4.z + r4.z; y.w = u4.w + r4.w;
            *(float4*)&Usf[k][pf][f * 4] = y;
        }
        __syncthreads();
#pragma unroll 4
        for (int k = 0; k < 32; ++k) {
            const float4* yr = (const float4*)&Usf[k][p][0];
            float4 y0 = yr[0], y1 = yr[1], y2 = yr[2], y3 = yr[3];
            float s = sbv;
            s += y0.x * wreg[0]  + y0.y * wreg[1]  + y0.z * wreg[2]  + y0.w * wreg[3];
            s += y1.x * wreg[4]  + y1.y * wreg[5]  + y1.z * wreg[6]  + y1.w * wreg[7];
            s += y2.x * wreg[8]  + y2.y * wreg[9]  + y2.z * wreg[10] + y2.w * wreg[11];
            s += y3.x * wreg[12] + y3.y * wreg[13] + y3.z * wreg[14] + y3.w * wreg[15];
            __half hs = __float2half(s);
            g_vh[bl][k0 + k][b][p] = hs;
            float sr = __half2float(hs);
            float auk = sau[j * 32 + k];
            aV += auk * sr;
            aQ += auk * sr * sr;
        }
    }
    atomicAdd(&g_pass0[bl][0][tid], aV);
    atomicAdd(&g_pass0[bl][1][tid], aQ);
}

// ---------------- kernel 5: fused EM routing, 2 v-passes ----------------
__device__ __forceinline__ void unp8(uint4 q, float* f) {
    const __half2* h = (const __half2*)&q;
#pragma unroll
    for (int i = 0; i < 4; ++i) {
        float2 t = __half22float2(h[i]);
        f[i * 2] = t.x; f[i * 2 + 1] = t.y;
    }
}

__global__ void k_em(const float* __restrict__ beta_u, const float* __restrict__ beta_a,
                     float* __restrict__ out) {
    const int bl = blockIdx.x;        // 196
    const int tid = threadIdx.x;      // 512
    const int warp = tid >> 5, lane = tid & 31;
    __shared__ float au[KKA];
    __shared__ float accv[32][17], acc2[32][17];
    __shared__ float accr[32];
    __shared__ float mu[32][17], i2s[32][17], sigs[32][17];
    __shared__ float lsum2[32], loga[32], aouts[32], rsum_sh[32];
    __shared__ float wred[16];
    __shared__ float sau_sh;

    for (int i = tid; i < KKA; i += 512) au[i] = g_au[bl][i];
    __syncthreads();
    // sum of au
    {
        float s = (tid < KKA) ? au[tid] : 0.f;
#pragma unroll
        for (int o = 16; o; o >>= 1) s += __shfl_xor_sync(~0u, s, o);
        if (lane == 0) wred[warp] = s;
        __syncthreads();
        if (tid == 0) { float t = 0.f; for (int i = 0; i < 16; ++i) t += wred[i]; sau_sh = t; }
        __syncthreads();
    }
    const __half* __restrict__ vb = &g_vh[bl][0][0][0];
    const int b = tid >> 4, q = tid & 15;
    const float LOG_LN2PI = logf(LN2PI);

    // ---- finalize iter 0 from votes-kernel stats (uniform r) ----
    {
        float rs = sau_sh * (1.f / 32.f);
        float iv = 1.f / (rs + EPSV);
        float sv = g_pass0[bl][0][tid];
        float sq = g_pass0[bl][1][tid];
        float m  = sv * (1.f / 32.f) * iv;
        float sg = sq * (1.f / 32.f) * iv - m * m + EPSV;
        mu[b][q] = m; sigs[b][q] = sg; i2s[b][q] = 0.5f / sg;
        if (tid < 32) rsum_sh[tid] = rs;
    }
    __syncthreads();
    if (tid < 32) {
        float ls = 0.f;
#pragma unroll
        for (int j = 0; j < 16; ++j) ls += logf(sigs[tid][j]);
        float cost = rsum_sh[tid] * (16.f * beta_u[tid] + 0.5f * ls);
        float z = 5.0e-4f * (beta_a[tid] - cost);
        float ao = 1.f / (1.f + expf(-z));
        aouts[tid] = ao; loga[tid] = logf(ao);
        lsum2[tid] = ls + 16.f * LOG_LN2PI;
    }
    __syncthreads();

    // ---- fused passes: e-step(it) + stats(it+1), it = 0, 1 ----
#pragma unroll 1
    for (int it = 0; it < 2; ++it) {
        for (int i = tid; i < 32 * 17; i += 512) { (&accv[0][0])[i] = 0.f; (&acc2[0][0])[i] = 0.f; }
        if (tid < 32) accr[tid] = 0.f;
        __syncthreads();
        float av[16], a2[16], ar = 0.f;
#pragma unroll
        for (int j = 0; j < 16; ++j) { av[j] = 0.f; a2[j] = 0.f; }
        const float myl2 = lsum2[lane];
        const float mylg = loga[lane];
        for (int k = warp; k < KKA; k += 16) {
            const uint4* vp = (const uint4*)(vb + (k * 32 + lane) * 16);
            uint4 q0 = vp[0], q1 = vp[1];
            float vv[16];
            unp8(q0, vv); unp8(q1, vv + 8);
            float s = 0.f;
#pragma unroll
            for (int j = 0; j < 16; ++j) {
                float d = vv[j] - mu[lane][j];
                s += d * d * i2s[lane][j];
            }
            float lnap = -0.5f * myl2 - s + mylg;
            float mx = lnap;
#pragma unroll
            for (int o = 16; o; o >>= 1) mx = fmaxf(mx, __shfl_xor_sync(~0u, mx, o));
            float e = expf(lnap - mx);
            float se = e;
#pragma unroll
            for (int o = 16; o; o >>= 1) se += __shfl_xor_sync(~0u, se, o);
            float c = (e / se) * au[k];
            ar += c;
#pragma unroll
            for (int j = 0; j < 16; ++j) {
                av[j] += c * vv[j];
                a2[j] += c * vv[j] * vv[j];
            }
        }
#pragma unroll
        for (int j = 0; j < 16; ++j) {
            atomicAdd(&accv[lane][j], av[j]);
            atomicAdd(&acc2[lane][j], a2[j]);
        }
        atomicAdd(&accr[lane], ar);
        __syncthreads();
        // finalize iter it+1
        {
            float rs = accr[b];
            float iv = 1.f / (rs + EPSV);
            float m  = accv[b][q] * iv;
            float sg = acc2[b][q] * iv - m * m + EPSV;
            mu[b][q] = m; sigs[b][q] = sg; i2s[b][q] = 0.5f / sg;
            if (tid < 32) rsum_sh[tid] = accr[tid];
        }
        __syncthreads();
        if (tid < 32) {
            float ls = 0.f;
#pragma unroll
            for (int j = 0; j < 16; ++j) ls += logf(sigs[tid][j]);
            float cost = rsum_sh[tid] * (16.f * beta_u[tid] + 0.5f * ls);
            float lam = (it == 0) ? 9.75e-4f : 1.42625e-3f;
            float z = lam * (beta_a[tid] - cost);
            float ao = 1.f / (1.f + expf(-z));
            aouts[tid] = ao; loga[tid] = logf(ao);
            lsum2[tid] = ls + 16.f * LOG_LN2PI;
        }
        __syncthreads();
    }
    // outputs: a_fin [BATCH][32][7][7] then pose_out [BATCH][512][7][7]
    int batch = bl / L, pos = bl - batch * L;
    if (tid < 32) out[(batch * 32 + tid) * L + pos] = aouts[tid];
    out[BATCH * 32 * L + (batch * 512 + tid) * L + pos] = mu[b][q];
}

// ---------------- launch ----------------
extern "C" void kernel_launch(void* const* d_in, const int* in_sizes, int n_in,
                              void* d_out, int out_size) {
    const float* a_in   = (const float*)d_in[0];
    const float* pose   = (const float*)d_in[1];
    const float* mposew = (const float*)d_in[2];
    const float* mposeb = (const float*)d_in[3];
    const float* freqw  = (const float*)d_in[4];
    const float* beta_u = (const float*)d_in[9];
    const float* beta_a = (const float*)d_in[10];
    float* out = (float*)d_out;

    k_build_h<<<16, KKA>>>(freqw);
    k_build_C<<<(16 * KKA * KKA + 255) / 256, 256>>>();
    k_unfold<<<(KKA * BL * PS + 255) / 256, 256>>>(pose, a_in);
    k_gemm<<<dim3(NPAD / 64, GM / 128), 256>>>();
    k_votes<<<dim3(BL, 3), 512>>>(mposew, mposeb);
    k_em<<<BL, 512>>>(beta_u, beta_a, out);
}